// round 15
// baseline (speedup 1.0000x reference)
#include <cuda_runtime.h>
#include <cuda_fp16.h>
#include <cstdint>
#include <math.h>

#define SEQ   4096
#define DM    2048
#define NH    16
#define NKV   4
#define HDIM  128
#define QW    (NH * HDIM)    /* 2048 */
#define KWW   (NKV * HDIM)   /* 512  */
#define QKVW  (QW + 2 * KWW) /* 3072 */

// ---------------- scratch (device globals; no allocations allowed) ----------
__device__ __half g_qkv[SEQ * QKVW];         // fp16 packed [Q|K|V] from QKV GEMM
__device__ __half g_h_hi[SEQ * DM];
__device__ __half g_w_hi[QKVW * DM];
__device__ __half g_wo_hi[DM * QW];
__device__ __half g_q_hi[SEQ * QW];
__device__ __half g_k_hi[SEQ * KWW];
__device__ __half g_a_hi[SEQ * QW];

// ---------------- helpers -----------------------------------------------------
__device__ __forceinline__ uint32_t smem_u32(const void* p) {
    uint32_t a;
    asm("{ .reg .u64 t; cvta.to.shared.u64 t, %1; cvt.u32.u64 %0, t; }"
        : "=r"(a) : "l"(p));
    return a;
}

__device__ __forceinline__ void cp16(uint32_t dst, const void* src) {
    asm volatile("cp.async.cg.shared.global [%0], [%1], 16;" :: "r"(dst), "l"(src));
}
#define CP_COMMIT() asm volatile("cp.async.commit_group;" ::: "memory")
#define CP_WAIT(n)  asm volatile("cp.async.wait_group %0;" :: "n"(n) : "memory")

#define LDSM4(r, addr)                                                        \
    asm volatile("ldmatrix.sync.aligned.m8n8.x4.shared.b16 {%0,%1,%2,%3}, [%4];" \
        : "=r"((r)[0]), "=r"((r)[1]), "=r"((r)[2]), "=r"((r)[3]) : "r"(addr))

#define LDSM4T(r, addr)                                                       \
    asm volatile("ldmatrix.sync.aligned.m8n8.x4.trans.shared.b16 {%0,%1,%2,%3}, [%4];" \
        : "=r"((r)[0]), "=r"((r)[1]), "=r"((r)[2]), "=r"((r)[3]) : "r"(addr))

#define MMA16816(d, a, b)                                                     \
    asm volatile("mma.sync.aligned.m16n8k16.row.col.f32.f16.f16.f32 "         \
        "{%0,%1,%2,%3}, {%4,%5,%6,%7}, {%8,%9}, {%0,%1,%2,%3};"               \
        : "+f"((d)[0]), "+f"((d)[1]), "+f"((d)[2]), "+f"((d)[3])              \
        : "r"((a)[0]), "r"((a)[1]), "r"((a)[2]), "r"((a)[3]),                 \
          "r"((b)[0]), "r"((b)[1]))

__device__ __forceinline__ uint32_t hpack2(float x, float y) {
    __half2 hp = __floats2half2_rn(x, y);
    return *reinterpret_cast<uint32_t*>(&hp);
}

// ============================================================================
// fused fp32 -> fp16 conversion for hidden + all weights (single launch)
// ============================================================================
#define N_H   (SEQ * DM)
#define N_WQ  (QW  * DM)
#define N_WK  (KWW * DM)
#define N_WV  (KWW * DM)
#define N_WO  (DM  * QW)
#define N_CTOT (N_H + N_WQ + N_WK + N_WV + N_WO)

__global__ void conv_all(const float* __restrict__ hidden,
                         const float* __restrict__ wq,
                         const float* __restrict__ wk,
                         const float* __restrict__ wv,
                         const float* __restrict__ wo,
                         __half* __restrict__ h_hi,
                         __half* __restrict__ w_hi,
                         __half* __restrict__ wo_hi)
{
    int i = (blockIdx.x * blockDim.x + threadIdx.x) * 4;
    if (i >= N_CTOT) return;
    const float* src; __half* dst; int off;
    if (i < N_H)                          { src = hidden; dst = h_hi;               off = i; }
    else if (i < N_H + N_WQ)              { src = wq; dst = w_hi;                   off = i - N_H; }
    else if (i < N_H + N_WQ + N_WK)       { src = wk; dst = w_hi + N_WQ;            off = i - N_H - N_WQ; }
    else if (i < N_H + N_WQ + N_WK + N_WV){ src = wv; dst = w_hi + N_WQ + N_WK;     off = i - N_H - N_WQ - N_WK; }
    else                                  { src = wo; dst = wo_hi;                  off = i - N_H - N_WQ - N_WK - N_WV; }
    float4 v = *(const float4*)(src + off);
    *(uint32_t*)(dst + off)     = hpack2(v.x, v.y);
    *(uint32_t*)(dst + off + 2) = hpack2(v.z, v.w);
}

// ============================================================================
// Pure fp16 mma.sync NT GEMM: C = A B^T, output fp32 or fp16 (templated).
// CTA 128x256, BK=32, 8 warps 2Mx4N (64x64), 4-stage cp.async pipeline.
// ============================================================================
#define BK        32
#define LDS_PAD   40
#define A_TILE_B  (128 * LDS_PAD * 2)
#define B_TILE_B  (256 * LDS_PAD * 2)
#define STAGE_B   (A_TILE_B + B_TILE_B)
#define NSTAGE    4
#define GEMM_SMEM (NSTAGE * STAGE_B)

template <typename OutT>
__global__ __launch_bounds__(256, 1) void gemm_f16(
    const __half* __restrict__ A, const __half* __restrict__ B,
    OutT* __restrict__ C, int N, int K)
{
    extern __shared__ char smem[];
    const uint32_t sb = smem_u32(smem);
    const int tid  = threadIdx.x;
    const int wid  = tid >> 5, lane = tid & 31;
    const int m0   = blockIdx.y * 128, n0 = blockIdx.x * 256;
    const int wm   = (wid & 1) * 64;
    const int wn   = (wid >> 1) * 64;

    const __half* a_p = A + (size_t)m0 * K;
    const __half* b_p = B + (size_t)n0 * K;

    const int a_row_l = lane & 15;
    const int a_colb  = ((lane >> 4) & 1) << 3;
    const int b_row_l = (lane & 7) + (((lane >> 4) & 1) << 3);
    const int b_colb  = ((lane >> 3) & 1) << 3;

    float d[4][8][4];
#pragma unroll
    for (int i = 0; i < 4; i++)
#pragma unroll
        for (int j = 0; j < 8; j++)
#pragma unroll
            for (int q = 0; q < 4; q++) d[i][j][q] = 0.f;

    const int nk = K / BK;

#define LOAD_STAGE(s, k0) do {                                                \
    uint32_t stb = sb + (uint32_t)(s) * STAGE_B;                              \
    _Pragma("unroll")                                                         \
    for (int it = 0; it < 2; it++) {                                          \
        int idx = tid + it * 256;                                             \
        int r = idx >> 2, c = idx & 3;                                        \
        cp16(stb + (uint32_t)(r * LDS_PAD + c * 8) * 2,                       \
             a_p + (size_t)r * K + (k0) + c * 8);                             \
    }                                                                         \
    _Pragma("unroll")                                                         \
    for (int it = 0; it < 4; it++) {                                          \
        int idx = tid + it * 256;                                             \
        int r = idx >> 2, c = idx & 3;                                        \
        cp16(stb + A_TILE_B + (uint32_t)(r * LDS_PAD + c * 8) * 2,            \
             b_p + (size_t)r * K + (k0) + c * 8);                             \
    }                                                                         \
    CP_COMMIT();                                                              \
} while (0)

    LOAD_STAGE(0, 0);
    LOAD_STAGE(1, BK);
    LOAD_STAGE(2, 2 * BK);

    for (int kt = 0; kt < nk; kt++) {
        if (kt + 3 < nk)      { LOAD_STAGE((kt + 3) % NSTAGE, (kt + 3) * BK); CP_WAIT(3); }
        else if (kt + 2 < nk) { CP_WAIT(2); }
        else if (kt + 1 < nk) { CP_WAIT(1); }
        else                  { CP_WAIT(0); }
        __syncthreads();

        const uint32_t stb = sb + (uint32_t)(kt % NSTAGE) * STAGE_B;
        const uint32_t AB  = stb;
        const uint32_t BB  = stb + A_TILE_B;

#pragma unroll
        for (int ks = 0; ks < BK; ks += 16) {
            uint32_t ah[4][4];
#pragma unroll
            for (int i = 0; i < 4; i++) {
                uint32_t off = (uint32_t)((wm + 16 * i + a_row_l) * LDS_PAD
                                          + ks + a_colb) * 2;
                LDSM4(ah[i], AB + off);
            }
#pragma unroll
            for (int jp = 0; jp < 4; jp++) {
                uint32_t bh[4];
                uint32_t off = (uint32_t)((wn + 16 * jp + b_row_l) * LDS_PAD
                                          + ks + b_colb) * 2;
                LDSM4(bh, BB + off);
#pragma unroll
                for (int i = 0; i < 4; i++) {
                    MMA16816(d[i][2*jp],   ah[i], bh);
                    MMA16816(d[i][2*jp+1], ah[i], bh + 2);
                }
            }
        }
        __syncthreads();
    }

    const int trow = lane >> 2, tcol = (lane & 3) * 2;
#pragma unroll
    for (int i = 0; i < 4; i++)
#pragma unroll
        for (int j = 0; j < 8; j++) {
            OutT* p = C + (size_t)(m0 + wm + 16 * i + trow) * N
                        + (n0 + wn + 8 * j + tcol);
            OutT* p2 = p + (size_t)8 * N;
            if constexpr (sizeof(OutT) == 2) {
                *(uint32_t*)p  = hpack2(d[i][j][0], d[i][j][1]);
                *(uint32_t*)p2 = hpack2(d[i][j][2], d[i][j][3]);
            } else {
                p[0]  = d[i][j][0]; p[1]  = d[i][j][1];
                p2[0] = d[i][j][2]; p2[1] = d[i][j][3];
            }
        }
}

// ============================================================================
// RoPE on fp16 qkv: Q heads -> g_q_hi, K heads -> g_k_hi. V stays in qkv.
// ============================================================================
__global__ void rope_qk(const __half* __restrict__ qkv,
                        const float* __restrict__ cosT,
                        const float* __restrict__ sinT,
                        __half* __restrict__ qhi, __half* __restrict__ khi)
{
    int idx = blockIdx.x * blockDim.x + threadIdx.x;
    if (idx >= SEQ * 20 * 64) return;
    int d  = idx & 63;
    int hh = (idx >> 6) % 20;
    int s  = idx / (20 * 64);
    const __half* p = qkv + (size_t)s * QKVW + hh * HDIM;
    float x1 = __half2float(p[d]), x2 = __half2float(p[d + 64]);
    float c  = cosT[s * HDIM + d];
    float sn = sinT[s * HDIM + d];
    float y1 = fmaf(x1, c, -x2 * sn);
    float y2 = fmaf(x2, c,  x1 * sn);
    if (hh < NH) {
        size_t o = (size_t)s * QW + hh * HDIM;
        qhi[o + d]      = __float2half_rn(y1);
        qhi[o + d + 64] = __float2half_rn(y2);
    } else {
        size_t o = (size_t)s * KWW + (hh - NH) * HDIM;
        khi[o + d]      = __float2half_rn(y1);
        khi[o + d + 64] = __float2half_rn(y2);
    }
}

// ============================================================================
// Tensor-core causal flash attention — fp16 operands, fp32 accum,
// fixed-base softmax. FAT-WARP variant: CTA = 128 q-rows, 4 warps x 32 rows,
// 128 threads. Each K/V fragment feeds 4 MMAs (2 M-tiles) -> LDSM:MMA halves.
// 64-row KV tiles double-buffered; 104 KB smem, ~235 regs -> 2 CTAs/SM.
// V read directly from packed qkv (row stride QKVW).
// ============================================================================
#define BQ      128
#define BKV     64
#define FL_STR  136
#define FL_QT   (BQ * FL_STR * 2)              /* 34816 */
#define FL_KT   (BKV * FL_STR * 2)             /* 17408 */
#define FL_STG  (2 * FL_KT)                    /* 34816 */
#define FLASH_SMEM (FL_QT + 2 * FL_STG)        /* 104448 */

__global__ __launch_bounds__(128, 2) void flash_mma(
    const __half* __restrict__ Qhi,
    const __half* __restrict__ Khi, const __half* __restrict__ Vsrc,
    __half* __restrict__ Ohi)
{
    extern __shared__ char smem[];
    const uint32_t sbm = smem_u32(smem);
    const uint32_t QHI = sbm;
    const uint32_t ST0 = sbm + FL_QT;

    const int qt  = (int)gridDim.x - 1 - (int)blockIdx.x;   // biggest first
    const int h   = blockIdx.y;
    const int kvh = h >> 2;
    const int tid = threadIdx.x, wid = tid >> 5, lane = tid & 31;
    const int qbase = qt * BQ;
    const int wm  = wid * 32;                  // 32 rows per warp
    const int nkt = 2 * qt + 2;                // 64-row KV tiles
    const float scale = 0.08838834764831845f;

    const int a_row = lane & 15;
    const int a_cb  = ((lane >> 4) & 1) << 3;
    const int b_row = (lane & 7) + (((lane >> 4) & 1) << 3);
    const int b_cb  = ((lane >> 3) & 1) << 3;
    const int v_row = (lane & 7) + (((lane >> 3) & 1) << 3);
    const int v_cb  = ((lane >> 4) & 1) << 3;
    const int r0    = lane >> 2;
    const int colq  = (lane & 3) * 2;

    // ---- Q tile -> smem (128 rows x 16 chunks = 2048 cp16 / 128 thr) ----
    {
        const size_t qoff = (size_t)qbase * QW + h * HDIM;
#pragma unroll
        for (int it = 0; it < 16; it++) {
            int idx = tid + it * 128;
            int r = idx >> 4, c = idx & 15;
            cp16(QHI + (uint32_t)(r * FL_STR + c * 8) * 2,
                 Qhi + qoff + (size_t)r * QW + c * 8);
        }
        CP_COMMIT();
    }

    // K from Khi (stride KWW), V from packed qkv (stride QKVW); 64 rows.
#define FL_LOAD(s, kb) do {                                                   \
    uint32_t stb_ = ST0 + (uint32_t)(s) * FL_STG;                             \
    const size_t kko_ = (size_t)(kb) * KWW  + kvh * HDIM;                     \
    const size_t vko_ = (size_t)(kb) * QKVW + kvh * HDIM;                     \
    _Pragma("unroll")                                                         \
    for (int it = 0; it < 8; it++) {                                          \
        int idx = tid + it * 128;                                             \
        int r = idx >> 4, c = idx & 15;                                       \
        uint32_t d_ = (uint32_t)(r * FL_STR + c * 8) * 2;                     \
        cp16(stb_ + 0 * FL_KT + d_, Khi  + kko_ + (size_t)r * KWW  + c * 8);  \
        cp16(stb_ + 1 * FL_KT + d_, Vsrc + vko_ + (size_t)r * QKVW + c * 8);  \
    }                                                                         \
    CP_COMMIT();                                                              \
} while (0)

    FL_LOAD(0, 0);
    CP_WAIT(1);
    __syncthreads();

    float l00 = 0.f, l01 = 0.f, l10 = 0.f, l11 = 0.f;
    float o[2][16][4];
#pragma unroll
    for (int mt = 0; mt < 2; mt++)
#pragma unroll
        for (int j = 0; j < 16; j++)
#pragma unroll
            for (int q = 0; q < 4; q++) o[mt][j][q] = 0.f;

    for (int kt = 0; kt < nkt; kt++) {
        if (kt + 1 < nkt) { FL_LOAD((kt + 1) & 1, (kt + 1) * BKV); CP_WAIT(1); }
        else              { CP_WAIT(0); }
        __syncthreads();

        const uint32_t stb = ST0 + (uint32_t)(kt & 1) * FL_STG;
        const uint32_t KH = stb, VH = stb + FL_KT;
        const int kbase = kt * BKV;

        // ---- S = Q K^T (2 M-tiles per warp) ----
        float s[2][8][4];
#pragma unroll
        for (int mt = 0; mt < 2; mt++)
#pragma unroll
            for (int j = 0; j < 8; j++)
#pragma unroll
                for (int q = 0; q < 4; q++) s[mt][j][q] = 0.f;

#pragma unroll
        for (int ks = 0; ks < 8; ks++) {
            uint32_t qf0[4], qf1[4];
            uint32_t q0 = (uint32_t)((wm + a_row) * FL_STR + ks * 16 + a_cb) * 2;
            LDSM4(qf0, QHI + q0);
            LDSM4(qf1, QHI + q0 + (uint32_t)(16 * FL_STR * 2));
#pragma unroll
            for (int jp = 0; jp < 4; jp++) {
                uint32_t bh[4];
                uint32_t koff = (uint32_t)((jp * 16 + b_row) * FL_STR
                                           + ks * 16 + b_cb) * 2;
                LDSM4(bh, KH + koff);
                MMA16816(s[0][2*jp],   qf0, bh);
                MMA16816(s[0][2*jp+1], qf0, bh + 2);
                MMA16816(s[1][2*jp],   qf1, bh);
                MMA16816(s[1][2*jp+1], qf1, bh + 2);
            }
        }

        // ---- fixed-base softmax: p = exp(scale*s) with causal mask ----
        if (kbase + BKV - 1 > qbase + wm) {    // warp-uniform diagonal check
#pragma unroll
            for (int mt = 0; mt < 2; mt++) {
                const int rowa = qbase + wm + mt * 16 + r0, rowb = rowa + 8;
                float la = 0.f, lb = 0.f;
#pragma unroll
                for (int j = 0; j < 8; j++) {
                    int c0 = kbase + j * 8 + colq, c1 = c0 + 1;
                    s[mt][j][0] = (c0 <= rowa) ? __expf(s[mt][j][0] * scale) : 0.f;
                    s[mt][j][1] = (c1 <= rowa) ? __expf(s[mt][j][1] * scale) : 0.f;
                    s[mt][j][2] = (c0 <= rowb) ? __expf(s[mt][j][2] * scale) : 0.f;
                    s[mt][j][3] = (c1 <= rowb) ? __expf(s[mt][j][3] * scale) : 0.f;
                    la += s[mt][j][0] + s[mt][j][1];
                    lb += s[mt][j][2] + s[mt][j][3];
                }
                if (mt == 0) { l00 += la; l01 += lb; }
                else         { l10 += la; l11 += lb; }
            }
        } else {
#pragma unroll
            for (int mt = 0; mt < 2; mt++) {
                float la = 0.f, lb = 0.f;
#pragma unroll
                for (int j = 0; j < 8; j++) {
                    s[mt][j][0] = __expf(s[mt][j][0] * scale);
                    s[mt][j][1] = __expf(s[mt][j][1] * scale);
                    s[mt][j][2] = __expf(s[mt][j][2] * scale);
                    s[mt][j][3] = __expf(s[mt][j][3] * scale);
                    la += s[mt][j][0] + s[mt][j][1];
                    lb += s[mt][j][2] + s[mt][j][3];
                }
                if (mt == 0) { l00 += la; l01 += lb; }
                else         { l10 += la; l11 += lb; }
            }
        }

        // ---- O += P V (each V fragment feeds both M-tiles) ----
#pragma unroll
        for (int t = 0; t < 4; t++) {
            uint32_t ph0[4], ph1[4];
            ph0[0] = hpack2(s[0][2*t][0],   s[0][2*t][1]);
            ph0[1] = hpack2(s[0][2*t][2],   s[0][2*t][3]);
            ph0[2] = hpack2(s[0][2*t+1][0], s[0][2*t+1][1]);
            ph0[3] = hpack2(s[0][2*t+1][2], s[0][2*t+1][3]);
            ph1[0] = hpack2(s[1][2*t][0],   s[1][2*t][1]);
            ph1[1] = hpack2(s[1][2*t][2],   s[1][2*t][3]);
            ph1[2] = hpack2(s[1][2*t+1][0], s[1][2*t+1][1]);
            ph1[3] = hpack2(s[1][2*t+1][2], s[1][2*t+1][3]);
#pragma unroll
            for (int jp = 0; jp < 8; jp++) {
                uint32_t vh[4];
                uint32_t voff = (uint32_t)((t * 16 + v_row) * FL_STR
                                           + jp * 16 + v_cb) * 2;
                LDSM4T(vh, VH + voff);
                MMA16816(o[0][2*jp],   ph0, vh);
                MMA16816(o[0][2*jp+1], ph0, vh + 2);
                MMA16816(o[1][2*jp],   ph1, vh);
                MMA16816(o[1][2*jp+1], ph1, vh + 2);
            }
        }
        __syncthreads();
    }

    // ---- epilogue: quad-reduce row sums, normalize, store ----
    l00 += __shfl_xor_sync(0xffffffffu, l00, 1);
    l00 += __shfl_xor_sync(0xffffffffu, l00, 2);
    l01 += __shfl_xor_sync(0xffffffffu, l01, 1);
    l01 += __shfl_xor_sync(0xffffffffu, l01, 2);
    l10 += __shfl_xor_sync(0xffffffffu, l10, 1);
    l10 += __shfl_xor_sync(0xffffffffu, l10, 2);
    l11 += __shfl_xor_sync(0xffffffffu, l11, 1);
    l11 += __shfl_xor_sync(0xffffffffu, l11, 2);
#pragma unroll
    for (int mt = 0; mt < 2; mt++) {
        const float inva = 1.f / (mt ? l10 : l00);
        const float invb = 1.f / (mt ? l11 : l01);
        const int rowa = qbase + wm + mt * 16 + r0;
        const size_t basea = (size_t)rowa * QW + h * HDIM;
        const size_t baseb = basea + (size_t)8 * QW;
#pragma unroll
        for (int j = 0; j < 16; j++) {
            int col = j * 8 + colq;
            *(uint32_t*)(Ohi + basea + col) =
                hpack2(o[mt][j][0] * inva, o[mt][j][1] * inva);
            *(uint32_t*)(Ohi + baseb + col) =
                hpack2(o[mt][j][2] * invb, o[mt][j][3] * invb);
        }
    }
}

// ============================================================================
// Launch
// ============================================================================
extern "C" void kernel_launch(void* const* d_in, const int* in_sizes, int n_in,
                              void* d_out, int out_size)
{
    const float* hidden = (const float*)d_in[0];
    const float* cosT   = (const float*)d_in[1];
    const float* sinT   = (const float*)d_in[2];
    const float* wq     = (const float*)d_in[4];
    const float* wk     = (const float*)d_in[5];
    const float* wv     = (const float*)d_in[6];
    const float* wo     = (const float*)d_in[7];
    float* out = (float*)d_out;

    __half *qkv, *h_hi, *w_hi, *wo_hi, *q_hi, *k_hi, *a_hi;
    cudaGetSymbolAddress((void**)&qkv,   g_qkv);
    cudaGetSymbolAddress((void**)&h_hi,  g_h_hi);
    cudaGetSymbolAddress((void**)&w_hi,  g_w_hi);
    cudaGetSymbolAddress((void**)&wo_hi, g_wo_hi);
    cudaGetSymbolAddress((void**)&q_hi,  g_q_hi);
    cudaGetSymbolAddress((void**)&k_hi,  g_k_hi);
    cudaGetSymbolAddress((void**)&a_hi,  g_a_hi);

    cudaFuncSetAttribute(gemm_f16<__half>,
                         cudaFuncAttributeMaxDynamicSharedMemorySize, GEMM_SMEM);
    cudaFuncSetAttribute(gemm_f16<float>,
                         cudaFuncAttributeMaxDynamicSharedMemorySize, GEMM_SMEM);
    cudaFuncSetAttribute(flash_mma,
                         cudaFuncAttributeMaxDynamicSharedMemorySize, FLASH_SMEM);

    conv_all<<<(N_CTOT / 4 + 255) / 256, 256>>>(
        hidden, wq, wk, wv, wo, h_hi, w_hi, wo_hi);

    gemm_f16<__half><<<dim3(QKVW / 256, SEQ / 128), 256, GEMM_SMEM>>>(
        h_hi, w_hi, qkv, QKVW, DM);

    rope_qk<<<(SEQ * 20 * 64 + 255) / 256, 256>>>(
        qkv, cosT, sinT, q_hi, k_hi);

    flash_mma<<<dim3(SEQ / BQ, NH), 128, FLASH_SMEM>>>(
        q_hi, k_hi, qkv + QW + KWW, a_hi);

    gemm_f16<float><<<dim3(DM / 256, SEQ / 128), 256, GEMM_SMEM>>>(
        a_hi, wo_hi, out, DM, DM);
}

// round 16
// speedup vs baseline: 1.0175x; 1.0175x over previous
#include <cuda_runtime.h>
#include <cuda_fp16.h>
#include <cstdint>
#include <math.h>

#define SEQ   4096
#define DM    2048
#define NH    16
#define NKV   4
#define HDIM  128
#define QW    (NH * HDIM)    /* 2048 */
#define KWW   (NKV * HDIM)   /* 512  */
#define QKVW  (QW + 2 * KWW) /* 3072 */

// ---------------- scratch (device globals; no allocations allowed) ----------
// qkv holds [Q|K|V] fp16. Q,K columns are PAIR-PERMUTED within each head:
// new col 2d <- old d, new col 2d+1 <- old d+64 (rope partners adjacent).
// QK^T is invariant under this shared permutation; V is unpermuted.
__device__ __half g_qkv[SEQ * QKVW];
__device__ __half g_h_hi[SEQ * DM];
__device__ __half g_w_hi[QKVW * DM];
__device__ __half g_wo_hi[DM * QW];
__device__ __half g_a_hi[SEQ * QW];

// ---------------- helpers -----------------------------------------------------
__device__ __forceinline__ uint32_t smem_u32(const void* p) {
    uint32_t a;
    asm("{ .reg .u64 t; cvta.to.shared.u64 t, %1; cvt.u32.u64 %0, t; }"
        : "=r"(a) : "l"(p));
    return a;
}

__device__ __forceinline__ void cp16(uint32_t dst, const void* src) {
    asm volatile("cp.async.cg.shared.global [%0], [%1], 16;" :: "r"(dst), "l"(src));
}
#define CP_COMMIT() asm volatile("cp.async.commit_group;" ::: "memory")
#define CP_WAIT(n)  asm volatile("cp.async.wait_group %0;" :: "n"(n) : "memory")

#define LDSM4(r, addr)                                                        \
    asm volatile("ldmatrix.sync.aligned.m8n8.x4.shared.b16 {%0,%1,%2,%3}, [%4];" \
        : "=r"((r)[0]), "=r"((r)[1]), "=r"((r)[2]), "=r"((r)[3]) : "r"(addr))

#define LDSM4T(r, addr)                                                       \
    asm volatile("ldmatrix.sync.aligned.m8n8.x4.trans.shared.b16 {%0,%1,%2,%3}, [%4];" \
        : "=r"((r)[0]), "=r"((r)[1]), "=r"((r)[2]), "=r"((r)[3]) : "r"(addr))

#define MMA16816(d, a, b)                                                     \
    asm volatile("mma.sync.aligned.m16n8k16.row.col.f32.f16.f16.f32 "         \
        "{%0,%1,%2,%3}, {%4,%5,%6,%7}, {%8,%9}, {%0,%1,%2,%3};"               \
        : "+f"((d)[0]), "+f"((d)[1]), "+f"((d)[2]), "+f"((d)[3])              \
        : "r"((a)[0]), "r"((a)[1]), "r"((a)[2]), "r"((a)[3]),                 \
          "r"((b)[0]), "r"((b)[1]))

__device__ __forceinline__ uint32_t hpack2(float x, float y) {
    __half2 hp = __floats2half2_rn(x, y);
    return *reinterpret_cast<uint32_t*>(&hp);
}

// ============================================================================
// fused fp32 -> fp16 conversion: hidden + weights, one launch.
// wq/wk output-feature rows are permuted: within each head,
// dst_row(d) = 2d (d<64) or 2(d-64)+1 (d>=64).
// ============================================================================
#define N_H   (SEQ * DM)
#define N_WQ  (QW  * DM)
#define N_WK  (KWW * DM)
#define N_WV  (KWW * DM)
#define N_WO  (DM  * QW)
#define N_CTOT (N_H + N_WQ + N_WK + N_WV + N_WO)

__device__ __forceinline__ int rope_perm_row(int r) {
    int head = r >> 7, rd = r & 127;
    return (head << 7) + ((rd < 64) ? (rd << 1) : (((rd - 64) << 1) | 1));
}

__global__ void conv_all(const float* __restrict__ hidden,
                         const float* __restrict__ wq,
                         const float* __restrict__ wk,
                         const float* __restrict__ wv,
                         const float* __restrict__ wo,
                         __half* __restrict__ h_hi,
                         __half* __restrict__ w_hi,
                         __half* __restrict__ wo_hi)
{
    int i = (blockIdx.x * blockDim.x + threadIdx.x) * 4;
    if (i >= N_CTOT) return;
    const float* src; __half* dst; int off; int permute = 0;
    if (i < N_H)                          { src = hidden; dst = h_hi;           off = i; }
    else if (i < N_H + N_WQ)              { src = wq; dst = w_hi;               off = i - N_H; permute = 1; }
    else if (i < N_H + N_WQ + N_WK)       { src = wk; dst = w_hi + N_WQ;        off = i - N_H - N_WQ; permute = 1; }
    else if (i < N_H + N_WQ + N_WK + N_WV){ src = wv; dst = w_hi + N_WQ + N_WK; off = i - N_H - N_WQ - N_WK; }
    else                                  { src = wo; dst = wo_hi;              off = i - N_H - N_WQ - N_WK - N_WV; }
    float4 v = *(const float4*)(src + off);
    int doff = off;
    if (permute) {
        int r = off / DM, c = off - r * DM;
        doff = rope_perm_row(r) * DM + c;
    }
    *(uint32_t*)(dst + doff)     = hpack2(v.x, v.y);
    *(uint32_t*)(dst + doff + 2) = hpack2(v.z, v.w);
}

// ============================================================================
// Pure fp16 mma.sync NT GEMM: C = A B^T, output fp32 or fp16 (templated).
// DO_ROPE: apply RoPE in the epilogue on fragment pairs (cols 2d, 2d+1 of
// each head hold rope partners thanks to the weight permutation). Applies
// only to Q|K column blocks (n0 < QW+KWW), which are 256-aligned.
// CTA 128x256, BK=32, 8 warps 2Mx4N (64x64), 4-stage cp.async pipeline.
// ============================================================================
#define BK        32
#define LDS_PAD   40
#define A_TILE_B  (128 * LDS_PAD * 2)
#define B_TILE_B  (256 * LDS_PAD * 2)
#define STAGE_B   (A_TILE_B + B_TILE_B)
#define NSTAGE    4
#define GEMM_SMEM (NSTAGE * STAGE_B)

template <typename OutT, bool DO_ROPE>
__global__ __launch_bounds__(256, 1) void gemm_f16(
    const __half* __restrict__ A, const __half* __restrict__ B,
    OutT* __restrict__ C, int N, int K,
    const float* __restrict__ cosT, const float* __restrict__ sinT)
{
    extern __shared__ char smem[];
    const uint32_t sb = smem_u32(smem);
    const int tid  = threadIdx.x;
    const int wid  = tid >> 5, lane = tid & 31;
    const int m0   = blockIdx.y * 128, n0 = blockIdx.x * 256;
    const int wm   = (wid & 1) * 64;
    const int wn   = (wid >> 1) * 64;

    const __half* a_p = A + (size_t)m0 * K;
    const __half* b_p = B + (size_t)n0 * K;

    const int a_row_l = lane & 15;
    const int a_colb  = ((lane >> 4) & 1) << 3;
    const int b_row_l = (lane & 7) + (((lane >> 4) & 1) << 3);
    const int b_colb  = ((lane >> 3) & 1) << 3;

    float d[4][8][4];
#pragma unroll
    for (int i = 0; i < 4; i++)
#pragma unroll
        for (int j = 0; j < 8; j++)
#pragma unroll
            for (int q = 0; q < 4; q++) d[i][j][q] = 0.f;

    const int nk = K / BK;

#define LOAD_STAGE(s, k0) do {                                                \
    uint32_t stb = sb + (uint32_t)(s) * STAGE_B;                              \
    _Pragma("unroll")                                                         \
    for (int it = 0; it < 2; it++) {                                          \
        int idx = tid + it * 256;                                             \
        int r = idx >> 2, c = idx & 3;                                        \
        cp16(stb + (uint32_t)(r * LDS_PAD + c * 8) * 2,                       \
             a_p + (size_t)r * K + (k0) + c * 8);                             \
    }                                                                         \
    _Pragma("unroll")                                                         \
    for (int it = 0; it < 4; it++) {                                          \
        int idx = tid + it * 256;                                             \
        int r = idx >> 2, c = idx & 3;                                        \
        cp16(stb + A_TILE_B + (uint32_t)(r * LDS_PAD + c * 8) * 2,            \
             b_p + (size_t)r * K + (k0) + c * 8);                             \
    }                                                                         \
    CP_COMMIT();                                                              \
} while (0)

    LOAD_STAGE(0, 0);
    LOAD_STAGE(1, BK);
    LOAD_STAGE(2, 2 * BK);

    for (int kt = 0; kt < nk; kt++) {
        if (kt + 3 < nk)      { LOAD_STAGE((kt + 3) % NSTAGE, (kt + 3) * BK); CP_WAIT(3); }
        else if (kt + 2 < nk) { CP_WAIT(2); }
        else if (kt + 1 < nk) { CP_WAIT(1); }
        else                  { CP_WAIT(0); }
        __syncthreads();

        const uint32_t stb = sb + (uint32_t)(kt % NSTAGE) * STAGE_B;
        const uint32_t AB  = stb;
        const uint32_t BB  = stb + A_TILE_B;

#pragma unroll
        for (int ks = 0; ks < BK; ks += 16) {
            uint32_t ah[4][4];
#pragma unroll
            for (int i = 0; i < 4; i++) {
                uint32_t off = (uint32_t)((wm + 16 * i + a_row_l) * LDS_PAD
                                          + ks + a_colb) * 2;
                LDSM4(ah[i], AB + off);
            }
#pragma unroll
            for (int jp = 0; jp < 4; jp++) {
                uint32_t bh[4];
                uint32_t off = (uint32_t)((wn + 16 * jp + b_row_l) * LDS_PAD
                                          + ks + b_colb) * 2;
                LDSM4(bh, BB + off);
#pragma unroll
                for (int i = 0; i < 4; i++) {
                    MMA16816(d[i][2*jp],   ah[i], bh);
                    MMA16816(d[i][2*jp+1], ah[i], bh + 2);
                }
            }
        }
        __syncthreads();
    }

    const int trow = lane >> 2, tcol = (lane & 3) * 2;
    const bool rope_blk = DO_ROPE && (n0 < QW + KWW);
#pragma unroll
    for (int i = 0; i < 4; i++)
#pragma unroll
        for (int j = 0; j < 8; j++) {
            if (rope_blk) {
                int col   = n0 + wn + 8 * j + tcol;        // even
                int d_idx = (col & 127) >> 1;
                int row0  = m0 + wm + 16 * i + trow;
                float c0 = cosT[row0 * HDIM + d_idx];
                float s0 = sinT[row0 * HDIM + d_idx];
                float c1 = cosT[(row0 + 8) * HDIM + d_idx];
                float s1 = sinT[(row0 + 8) * HDIM + d_idx];
                float x1 = d[i][j][0], x2 = d[i][j][1];
                d[i][j][0] = fmaf(x1, c0, -x2 * s0);
                d[i][j][1] = fmaf(x2, c0,  x1 * s0);
                x1 = d[i][j][2]; x2 = d[i][j][3];
                d[i][j][2] = fmaf(x1, c1, -x2 * s1);
                d[i][j][3] = fmaf(x2, c1,  x1 * s1);
            }
            OutT* p  = C + (size_t)(m0 + wm + 16 * i + trow) * N
                         + (n0 + wn + 8 * j + tcol);
            OutT* p2 = p + (size_t)8 * N;
            if constexpr (sizeof(OutT) == 2) {
                *(uint32_t*)p  = hpack2(d[i][j][0], d[i][j][1]);
                *(uint32_t*)p2 = hpack2(d[i][j][2], d[i][j][3]);
            } else {
                p[0]  = d[i][j][0]; p[1]  = d[i][j][1];
                p2[0] = d[i][j][2]; p2[1] = d[i][j][3];
            }
        }
}

// ============================================================================
// Tensor-core causal flash attention — fp16 operands, fp32 accum,
// fixed-base softmax. Q/K/V all read directly from packed qkv (stride QKVW;
// Q,K pair-permuted — QK^T invariant). CTA = 64 q-rows x head, 4 warps x 16
// rows, 128 threads, Q reg-cached, 64-row KV tiles double-buffered;
// 87 KB smem -> 2 CTAs/SM (best-known R14 config).
// ============================================================================
#define BQ      64
#define BKV     64
#define FL_STR  136
#define FL_QT   (BQ * FL_STR * 2)              /* 17408 */
#define FL_KT   (BKV * FL_STR * 2)             /* 17408 */
#define FL_STG  (2 * FL_KT)                    /* 34816 */
#define FLASH_SMEM (FL_QT + 2 * FL_STG)        /* 87040 */

__global__ __launch_bounds__(128, 2) void flash_mma(
    const __half* __restrict__ qkv, __half* __restrict__ Ohi)
{
    extern __shared__ char smem[];
    const uint32_t sbm = smem_u32(smem);
    const uint32_t QHI = sbm;
    const uint32_t ST0 = sbm + FL_QT;

    const int qt  = (int)gridDim.x - 1 - (int)blockIdx.x;   // biggest first
    const int h   = blockIdx.y;
    const int kvh = h >> 2;
    const int tid = threadIdx.x, wid = tid >> 5, lane = tid & 31;
    const int qbase = qt * BQ;
    const int wm  = wid * 16;
    const int nkt = qt + 1;
    const float scale = 0.08838834764831845f;

    const int a_row = lane & 15;
    const int a_cb  = ((lane >> 4) & 1) << 3;
    const int b_row = (lane & 7) + (((lane >> 4) & 1) << 3);
    const int b_cb  = ((lane >> 3) & 1) << 3;
    const int v_row = (lane & 7) + (((lane >> 3) & 1) << 3);
    const int v_cb  = ((lane >> 4) & 1) << 3;
    const int r0    = lane >> 2;
    const int colq  = (lane & 3) * 2;

    // ---- Q tile -> smem (from qkv, stride QKVW) ----
    {
        const __half* qsrc = qkv + (size_t)qbase * QKVW + h * HDIM;
#pragma unroll
        for (int it = 0; it < 8; it++) {
            int idx = tid + it * 128;
            int r = idx >> 4, c = idx & 15;
            cp16(QHI + (uint32_t)(r * FL_STR + c * 8) * 2,
                 qsrc + (size_t)r * QKVW + c * 8);
        }
        CP_COMMIT();
    }

    // K and V from packed qkv, both stride QKVW.
#define FL_LOAD(s, kb) do {                                                   \
    uint32_t stb_ = ST0 + (uint32_t)(s) * FL_STG;                             \
    const __half* ksrc_ = qkv + (size_t)(kb) * QKVW + QW + kvh * HDIM;        \
    const __half* vsrc_ = ksrc_ + KWW;                                        \
    _Pragma("unroll")                                                         \
    for (int it = 0; it < 8; it++) {                                          \
        int idx = tid + it * 128;                                             \
        int r = idx >> 4, c = idx & 15;                                       \
        uint32_t d_ = (uint32_t)(r * FL_STR + c * 8) * 2;                     \
        cp16(stb_ + 0 * FL_KT + d_, ksrc_ + (size_t)r * QKVW + c * 8);        \
        cp16(stb_ + 1 * FL_KT + d_, vsrc_ + (size_t)r * QKVW + c * 8);        \
    }                                                                         \
    CP_COMMIT();                                                              \
} while (0)

    FL_LOAD(0, 0);

    // ---- cache Q fragments in registers ----
    uint32_t qh[8][4];
    CP_WAIT(1);
    __syncthreads();
#pragma unroll
    for (int ks = 0; ks < 8; ks++) {
        uint32_t qoff = (uint32_t)((wm + a_row) * FL_STR + ks * 16 + a_cb) * 2;
        LDSM4(qh[ks], QHI + qoff);
    }

    float l0 = 0.f, l1 = 0.f;
    float o[16][4];
#pragma unroll
    for (int j = 0; j < 16; j++)
#pragma unroll
        for (int q = 0; q < 4; q++) o[j][q] = 0.f;

    for (int kt = 0; kt < nkt; kt++) {
        if (kt + 1 < nkt) { FL_LOAD((kt + 1) & 1, (kt + 1) * BKV); CP_WAIT(1); }
        else              { CP_WAIT(0); }
        __syncthreads();

        const uint32_t stb = ST0 + (uint32_t)(kt & 1) * FL_STG;
        const uint32_t KH = stb, VH = stb + FL_KT;
        const int kbase = kt * BKV;

        // ---- S = Q K^T ----
        float s[8][4];
#pragma unroll
        for (int j = 0; j < 8; j++)
#pragma unroll
            for (int q = 0; q < 4; q++) s[j][q] = 0.f;

#pragma unroll
        for (int ks = 0; ks < 8; ks++) {
#pragma unroll
            for (int jp = 0; jp < 4; jp++) {
                uint32_t bh[4];
                uint32_t koff = (uint32_t)((jp * 16 + b_row) * FL_STR
                                           + ks * 16 + b_cb) * 2;
                LDSM4(bh, KH + koff);
                MMA16816(s[2*jp],   qh[ks], bh);
                MMA16816(s[2*jp+1], qh[ks], bh + 2);
            }
        }

        // ---- fixed-base softmax: p = exp(scale*s) with causal mask ----
        if (kbase + BKV - 1 > qbase + wm) {
            const int row0g = qbase + wm + r0, row1g = row0g + 8;
#pragma unroll
            for (int j = 0; j < 8; j++) {
                int c0 = kbase + j * 8 + colq, c1 = c0 + 1;
                s[j][0] = (c0 <= row0g) ? __expf(s[j][0] * scale) : 0.f;
                s[j][1] = (c1 <= row0g) ? __expf(s[j][1] * scale) : 0.f;
                s[j][2] = (c0 <= row1g) ? __expf(s[j][2] * scale) : 0.f;
                s[j][3] = (c1 <= row1g) ? __expf(s[j][3] * scale) : 0.f;
                l0 += s[j][0] + s[j][1];
                l1 += s[j][2] + s[j][3];
            }
        } else {
#pragma unroll
            for (int j = 0; j < 8; j++) {
                s[j][0] = __expf(s[j][0] * scale);
                s[j][1] = __expf(s[j][1] * scale);
                s[j][2] = __expf(s[j][2] * scale);
                s[j][3] = __expf(s[j][3] * scale);
                l0 += s[j][0] + s[j][1];
                l1 += s[j][2] + s[j][3];
            }
        }

        // ---- O += P V ----
#pragma unroll
        for (int t = 0; t < 4; t++) {
            uint32_t ph[4];
            ph[0] = hpack2(s[2*t][0],   s[2*t][1]);
            ph[1] = hpack2(s[2*t][2],   s[2*t][3]);
            ph[2] = hpack2(s[2*t+1][0], s[2*t+1][1]);
            ph[3] = hpack2(s[2*t+1][2], s[2*t+1][3]);
#pragma unroll
            for (int jp = 0; jp < 8; jp++) {
                uint32_t vh[4];
                uint32_t voff = (uint32_t)((t * 16 + v_row) * FL_STR
                                           + jp * 16 + v_cb) * 2;
                LDSM4T(vh, VH + voff);
                MMA16816(o[2*jp],   ph, vh);
                MMA16816(o[2*jp+1], ph, vh + 2);
            }
        }
        __syncthreads();
    }

    // ---- epilogue: quad-reduce row sums, normalize, store ----
    l0 += __shfl_xor_sync(0xffffffffu, l0, 1);
    l0 += __shfl_xor_sync(0xffffffffu, l0, 2);
    l1 += __shfl_xor_sync(0xffffffffu, l1, 1);
    l1 += __shfl_xor_sync(0xffffffffu, l1, 2);
    const float inv0 = 1.f / l0, inv1 = 1.f / l1;
    const int row0g = qbase + wm + r0;
    const size_t base0 = (size_t)row0g * QW + h * HDIM;
    const size_t base1 = base0 + (size_t)8 * QW;
#pragma unroll
    for (int j = 0; j < 16; j++) {
        int col = j * 8 + colq;
        *(uint32_t*)(Ohi + base0 + col) = hpack2(o[j][0] * inv0, o[j][1] * inv0);
        *(uint32_t*)(Ohi + base1 + col) = hpack2(o[j][2] * inv1, o[j][3] * inv1);
    }
}

// ============================================================================
// Launch
// ============================================================================
extern "C" void kernel_launch(void* const* d_in, const int* in_sizes, int n_in,
                              void* d_out, int out_size)
{
    const float* hidden = (const float*)d_in[0];
    const float* cosT   = (const float*)d_in[1];
    const float* sinT   = (const float*)d_in[2];
    const float* wq     = (const float*)d_in[4];
    const float* wk     = (const float*)d_in[5];
    const float* wv     = (const float*)d_in[6];
    const float* wo     = (const float*)d_in[7];
    float* out = (float*)d_out;

    __half *qkv, *h_hi, *w_hi, *wo_hi, *a_hi;
    cudaGetSymbolAddress((void**)&qkv,   g_qkv);
    cudaGetSymbolAddress((void**)&h_hi,  g_h_hi);
    cudaGetSymbolAddress((void**)&w_hi,  g_w_hi);
    cudaGetSymbolAddress((void**)&wo_hi, g_wo_hi);
    cudaGetSymbolAddress((void**)&a_hi,  g_a_hi);

    cudaFuncSetAttribute((const void*)gemm_f16<__half, true>,
                         cudaFuncAttributeMaxDynamicSharedMemorySize, GEMM_SMEM);
    cudaFuncSetAttribute((const void*)gemm_f16<float, false>,
                         cudaFuncAttributeMaxDynamicSharedMemorySize, GEMM_SMEM);
    cudaFuncSetAttribute(flash_mma,
                         cudaFuncAttributeMaxDynamicSharedMemorySize, FLASH_SMEM);

    conv_all<<<(N_CTOT / 4 + 255) / 256, 256>>>(
        hidden, wq, wk, wv, wo, h_hi, w_hi, wo_hi);

    gemm_f16<__half, true><<<dim3(QKVW / 256, SEQ / 128), 256, GEMM_SMEM>>>(
        h_hi, w_hi, qkv, QKVW, DM, cosT, sinT);

    flash_mma<<<dim3(SEQ / BQ, NH), 128, FLASH_SMEM>>>(qkv, a_hi);

    gemm_f16<float, false><<<dim3(DM / 256, SEQ / 128), 256, GEMM_SMEM>>>(
        a_hi, wo_hi, out, DM, DM, nullptr, nullptr);
}